// round 3
// baseline (speedup 1.0000x reference)
#include <cuda_runtime.h>
#include <math.h>
#include <stdint.h>

// Problem constants (fixed by the reference)
#define NN 8192
#define KK 16
#define GAMMA_MIN 0.9f
#define GAMMA_MAX 0.9995f

#define ROWS_PER_BLOCK 32
#define THREADS 256
#define N8 (NN / 8)   // 1024 groups of 8 floats per row

// 256-bit vector of 8 fp32 (as uint for .b32 constraints)
struct V8 { float x0,x1,x2,x3,x4,x5,x6,x7; };

__device__ __forceinline__ void stg_cs_v8(float* p, const V8& v) {
    asm volatile(
        "st.global.cs.v8.b32 [%0], {%1,%2,%3,%4,%5,%6,%7,%8};"
        :: "l"(p),
           "r"(__float_as_uint(v.x0)), "r"(__float_as_uint(v.x1)),
           "r"(__float_as_uint(v.x2)), "r"(__float_as_uint(v.x3)),
           "r"(__float_as_uint(v.x4)), "r"(__float_as_uint(v.x5)),
           "r"(__float_as_uint(v.x6)), "r"(__float_as_uint(v.x7))
        : "memory");
}

__device__ __forceinline__ V8 ldg_nc_v8(const float* p) {
    uint32_t a,b,c,d,e,f,g,h;
    asm volatile(
        "ld.global.nc.v8.b32 {%0,%1,%2,%3,%4,%5,%6,%7}, [%8];"
        : "=r"(a),"=r"(b),"=r"(c),"=r"(d),"=r"(e),"=r"(f),"=r"(g),"=r"(h)
        : "l"(p));
    V8 v;
    v.x0=__uint_as_float(a); v.x1=__uint_as_float(b);
    v.x2=__uint_as_float(c); v.x3=__uint_as_float(d);
    v.x4=__uint_as_float(e); v.x5=__uint_as_float(f);
    v.x6=__uint_as_float(g); v.x7=__uint_as_float(h);
    return v;
}

// ---------------------------------------------------------------------------
// Fused single kernel (see R1/R2 notes).
//   Phase A: gammas + per-row nonzero compaction of c[k] = gamma_k * v[k][n].
//   Phase B: W[n][m] = sum_i c_i * u[k_i][m], streamed out as 256-bit stores.
// ---------------------------------------------------------------------------
__global__ __launch_bounds__(THREADS)
void wslow_fused_kernel(const float* __restrict__ eta,
                        const float* __restrict__ v,
                        const float* __restrict__ u,
                        float* __restrict__ out) {
    const int m8 = blockIdx.x * THREADS + threadIdx.x;   // 8-float column group
    const int n0 = blockIdx.y * ROWS_PER_BLOCK;          // first row of tile
    const int t  = threadIdx.x;

    __shared__ float s_gam[KK];
    __shared__ int   s_nnz[ROWS_PER_BLOCK];
    __shared__ int   s_k[ROWS_PER_BLOCK][KK];
    __shared__ float s_c[ROWS_PER_BLOCK][KK];

    // --- Phase A1: gammas (16 threads) ---
    if (t < KK) {
        float e = eta[t];
        float s = 1.0f / (1.0f + expf(-e));
        s_gam[t] = GAMMA_MIN + (GAMMA_MAX - GAMMA_MIN) * s;
    }
    __syncthreads();

    // --- Phase A2: per-row compaction (32 threads, one row each) ---
    if (t < ROWS_PER_BLOCK) {
        const int n = n0 + t;
        int cnt = 0;
#pragma unroll
        for (int k = 0; k < KK; k++) {
            float c = s_gam[k] * v[k * NN + n];
            if (c != 0.0f) {
                s_k[t][cnt] = k;
                s_c[t][cnt] = c;
                cnt++;
            }
        }
        s_nnz[t] = cnt;
    }
    __syncthreads();

    // --- Phase B: streamed outer-product accumulation (256-bit I/O) ---
    float* o = out + (size_t)n0 * NN + (size_t)m8 * 8;

    int kprev = -1;
    V8  uv = {0,0,0,0,0,0,0,0};

#pragma unroll 8
    for (int r = 0; r < ROWS_PER_BLOCK; r++) {
        V8 acc = {0,0,0,0,0,0,0,0};
        const int nn = s_nnz[r];
        for (int i = 0; i < nn; i++) {
            const int k = s_k[r][i];
            if (k != kprev) {                               // block-uniform
                uv = ldg_nc_v8(u + (size_t)k * NN + (size_t)m8 * 8);
                kprev = k;
            }
            const float c = s_c[r][i];
            acc.x0 = fmaf(c, uv.x0, acc.x0);
            acc.x1 = fmaf(c, uv.x1, acc.x1);
            acc.x2 = fmaf(c, uv.x2, acc.x2);
            acc.x3 = fmaf(c, uv.x3, acc.x3);
            acc.x4 = fmaf(c, uv.x4, acc.x4);
            acc.x5 = fmaf(c, uv.x5, acc.x5);
            acc.x6 = fmaf(c, uv.x6, acc.x6);
            acc.x7 = fmaf(c, uv.x7, acc.x7);
        }
        stg_cs_v8(o, acc);                                  // 256-bit streaming
        o += NN;
    }
}

// ---------------------------------------------------------------------------
extern "C" void kernel_launch(void* const* d_in, const int* in_sizes, int n_in,
                              void* d_out, int out_size) {
    const float* eta = (const float*)d_in[0];   // [16]
    const float* v   = (const float*)d_in[1];   // [16, 8192]
    const float* u   = (const float*)d_in[2];   // [16, 8192]
    float* out = (float*)d_out;                 // [8192, 8192] fp32

    dim3 grid(N8 / THREADS, NN / ROWS_PER_BLOCK);   // (4, 256)
    wslow_fused_kernel<<<grid, THREADS>>>(eta, v, u, out);
}

// round 4
// speedup vs baseline: 1.0943x; 1.0943x over previous
#include <cuda_runtime.h>
#include <math.h>

// Problem constants (fixed by the reference)
#define NN 8192
#define KK 16
#define GAMMA_MIN 0.9f
#define GAMMA_MAX 0.9995f

#define ROWS_PER_BLOCK 16      // R4: halved from 32 -> 4096 blocks, finer waves
#define THREADS 256
#define N4 (NN / 4)            // 2048 float4 per row

// ---------------------------------------------------------------------------
// Fused single kernel (R2 structure, float4 stores, 32 regs, 8 blocks/SM).
//   Phase A: gammas + per-row nonzero compaction of c[k] = gamma_k * v[k][n]
//            (general: handles any nnz in [0,16]).
//   Phase B: W[n][m] = sum_i c_i * u[k_i][m]; register-cached u vector,
//            128-bit streaming stores.
// ---------------------------------------------------------------------------
__global__ __launch_bounds__(THREADS)
void wslow_fused_kernel(const float* __restrict__ eta,
                        const float* __restrict__ v,
                        const float* __restrict__ u,
                        float* __restrict__ out) {
    const int m4 = blockIdx.x * THREADS + threadIdx.x;   // float4 column index
    const int n0 = blockIdx.y * ROWS_PER_BLOCK;          // first row of tile
    const int t  = threadIdx.x;

    __shared__ float s_gam[KK];
    __shared__ int   s_nnz[ROWS_PER_BLOCK];
    __shared__ int   s_k[ROWS_PER_BLOCK][KK];
    __shared__ float s_c[ROWS_PER_BLOCK][KK];

    // --- Phase A1: gammas (16 threads) ---
    if (t < KK) {
        float e = eta[t];
        float s = 1.0f / (1.0f + expf(-e));
        s_gam[t] = GAMMA_MIN + (GAMMA_MAX - GAMMA_MIN) * s;
    }
    __syncthreads();

    // --- Phase A2: per-row compaction (one thread per row) ---
    if (t < ROWS_PER_BLOCK) {
        const int n = n0 + t;
        int cnt = 0;
#pragma unroll
        for (int k = 0; k < KK; k++) {
            float c = s_gam[k] * v[k * NN + n];
            if (c != 0.0f) {
                s_k[t][cnt] = k;
                s_c[t][cnt] = c;
                cnt++;
            }
        }
        s_nnz[t] = cnt;
    }
    __syncthreads();

    // --- Phase B: streamed outer-product accumulation ---
    const float4* __restrict__ u4 = reinterpret_cast<const float4*>(u);
    float4* __restrict__ o4 = reinterpret_cast<float4*>(out) + (size_t)n0 * N4 + m4;

    int    kprev = -1;
    float4 uv    = make_float4(0.f, 0.f, 0.f, 0.f);

#pragma unroll 8
    for (int r = 0; r < ROWS_PER_BLOCK; r++) {
        float4 acc = make_float4(0.f, 0.f, 0.f, 0.f);
        const int nn = s_nnz[r];
        for (int i = 0; i < nn; i++) {
            const int k = s_k[r][i];
            if (k != kprev) {                 // block-uniform branch
                uv = __ldg(&u4[k * N4 + m4]); // L1/L2-resident
                kprev = k;
            }
            const float c = s_c[r][i];
            acc.x = fmaf(c, uv.x, acc.x);
            acc.y = fmaf(c, uv.y, acc.y);
            acc.z = fmaf(c, uv.z, acc.z);
            acc.w = fmaf(c, uv.w, acc.w);
        }
        __stcs(o4, acc);                      // streaming 128-bit store
        o4 += N4;
    }
}

// ---------------------------------------------------------------------------
extern "C" void kernel_launch(void* const* d_in, const int* in_sizes, int n_in,
                              void* d_out, int out_size) {
    const float* eta = (const float*)d_in[0];   // [16]
    const float* v   = (const float*)d_in[1];   // [16, 8192]
    const float* u   = (const float*)d_in[2];   // [16, 8192]
    float* out = (float*)d_out;                 // [8192, 8192] fp32

    dim3 grid(N4 / THREADS, NN / ROWS_PER_BLOCK);   // (8, 512) = 4096 blocks
    wslow_fused_kernel<<<grid, THREADS>>>(eta, v, u, out);
}